// round 8
// baseline (speedup 1.0000x reference)
#include <cuda_runtime.h>
#include <cstdint>

// Problem constants (from reference):
//   B=256, P=4096, H=W=512
// Inputs (metadata order):
//   d_in[0]: indices   int32  [B, P, 2]   (JAX x64 disabled: jnp.int64 request -> int32)
//   d_in[1]: num_valid int32  [B]
//   d_in[2]: feats     float32[B, P, 1]
// Output: float32 [B, H, W]

#define B_  256
#define P_  4096
#define H_  512
#define W_  512
#define HW_ (H_ * W_)

#define THREADS_    1024
#define BPC_        2                           // batches per CTA (pipeline depth)
#define CTAS_       (B_ / BPC_)                 // 128 CTAs -> single wave
#define SMEM_BYTES  32768                       // 32 KB zero staging buffer
#define SLICE_BYTES (HW_ * 4)                   // 1 MB per batch
#define N_CHUNKS    (SLICE_BYTES / SMEM_BYTES)  // 32 bulk stores per batch

__device__ __forceinline__ uint32_t smem_u32(const void* p) {
    uint32_t a;
    asm("{ .reg .u64 t; cvta.to.shared.u64 t, %1; cvt.u32.u64 %0, t; }"
        : "=r"(a) : "l"(p));
    return a;
}

__device__ __forceinline__ void scatter_batch(const int2* __restrict__ ib,
                                              const float* __restrict__ fb,
                                              int nv,
                                              float* __restrict__ slice)
{
    #pragma unroll
    for (int k = 0; k < P_ / THREADS_; k++) {        // 4 points per thread
        const int p = threadIdx.x + k * THREADS_;
        if (p < nv) {
            const int2  rc = __ldg(ib + p);
            const float v  = __ldg(fb + p);
            if ((unsigned)rc.x < H_ && (unsigned)rc.y < W_) {
                atomicAdd(slice + rc.x * W_ + rc.y, v);
            }
        }
    }
}

__global__ __launch_bounds__(THREADS_, 1)
void scatter_densify_pipe_kernel(const int* __restrict__ indices,
                                 const int* __restrict__ num_valid,
                                 const float* __restrict__ feats,
                                 float* __restrict__ out)
{
    __shared__ __align__(128) float4 zbuf[SMEM_BYTES / 16];

    const int b0 = blockIdx.x * BPC_;
    float* base = out + (size_t)b0 * HW_;

    // Hoist scalar loads; latency hides under smem zeroing / TMA issue.
    const int nv0 = num_valid[b0];
    const int nv1 = num_valid[b0 + 1];

    // ---- Zero the 32 KB SMEM staging buffer ----
    const float4 z = make_float4(0.f, 0.f, 0.f, 0.f);
    #pragma unroll
    for (int i = threadIdx.x; i < SMEM_BYTES / 16; i += THREADS_) {
        zbuf[i] = z;
    }
    __syncthreads();

    // ---- Issue bulk zero-stores for BOTH batches, one commit group each ----
    if (threadIdx.x == 0) {
        asm volatile("fence.proxy.async.shared::cta;" ::: "memory");
        const uint32_t src = smem_u32(zbuf);
        #pragma unroll
        for (int kb = 0; kb < BPC_; kb++) {
            char* dst = reinterpret_cast<char*>(base + (size_t)kb * HW_);
            #pragma unroll
            for (int c = 0; c < N_CHUNKS; c++) {
                asm volatile(
                    "cp.async.bulk.global.shared::cta.bulk_group [%0], [%1], %2;"
                    :: "l"(dst + (size_t)c * SMEM_BYTES), "r"(src), "n"(SMEM_BYTES)
                    : "memory");
            }
            asm volatile("cp.async.bulk.commit_group;" ::: "memory");
        }
    }

    const int2*  ib = reinterpret_cast<const int2*>(indices) + (size_t)b0 * P_;
    const float* fb = feats + (size_t)b0 * P_;

    // ---- Pipeline: scatter batch 0 while batch 1's writes drain ----
    if (threadIdx.x == 0) {
        asm volatile("cp.async.bulk.wait_group 1;" ::: "memory");  // batch 0 committed
    }
    __syncthreads();
    scatter_batch(ib, fb, nv0, base);

    if (threadIdx.x == 0) {
        asm volatile("cp.async.bulk.wait_group 0;" ::: "memory");  // batch 1 committed
    }
    __syncthreads();
    scatter_batch(ib + P_, fb + P_, nv1, base + HW_);
}

extern "C" void kernel_launch(void* const* d_in, const int* in_sizes, int n_in,
                              void* d_out, int out_size)
{
    const int*   indices = (const int*)d_in[0];
    const int*   nvalid  = (const int*)d_in[1];
    const float* feats   = (const float*)d_in[2];
    float*       out     = (float*)d_out;

    scatter_densify_pipe_kernel<<<CTAS_, THREADS_>>>(indices, nvalid, feats, out);
}